// round 11
// baseline (speedup 1.0000x reference)
#include <cuda_runtime.h>
#include <cstdint>

#define NB 16384
#define NT 1024
#define HH 64
#define TPB 128               // 4 fully independent warps; 2 elements/warp
#define EPB 8                 // elements per block
#define GRID (NB / EPB)       // 2048 blocks -> 8192 warps

#define L2E2 2.8853900817779268f   // 2*log2(e), folded into W1/b1/W2/b2

typedef unsigned long long u64;

static __device__ __forceinline__ u64 fma2(u64 a, u64 b, u64 c) {
    u64 d;
    asm("fma.rn.f32x2 %0, %1, %2, %3;" : "=l"(d) : "l"(a), "l"(b), "l"(c));
    return d;
}
static __device__ __forceinline__ u64 add2(u64 a, u64 b) {
    u64 d;
    asm("add.rn.f32x2 %0, %1, %2;" : "=l"(d) : "l"(a), "l"(b));
    return d;
}
static __device__ __forceinline__ u64 pk(float a, float b) {
    u64 d;
    asm("mov.b64 %0, {%1, %2};" : "=l"(d) : "f"(a), "f"(b));
    return d;
}
static __device__ __forceinline__ u64 dup2(float a) {
    u64 d;
    asm("mov.b64 %0, {%1, %1};" : "=l"(d) : "f"(a));
    return d;
}
static __device__ __forceinline__ void upk(u64 v, float& a, float& b) {
    asm("mov.b64 {%0, %1}, %2;" : "=f"(a), "=f"(b) : "l"(v));
}
static __device__ __forceinline__ u64 shfl_xor64(u64 v, int m) {
    uint32_t lo = (uint32_t)v, hi = (uint32_t)(v >> 32);
    lo = __shfl_xor_sync(0xffffffffu, lo, m);
    hi = __shfl_xor_sync(0xffffffffu, hi, m);
    return ((u64)hi << 32) | lo;
}
// tanh with prescaled arg a = 2*log2(e)*x: tanh(x) = 1 - 2/(2^a + 1).
// Validated at rel_err ~3e-7 over 1023 steps (rounds 1-10).
static __device__ __forceinline__ float tanh_pre(float a) {
    float e, r;
    asm("ex2.approx.f32 %0, %1;" : "=f"(e) : "f"(a));
    asm("rcp.approx.f32 %0, %1;" : "=f"(r) : "f"(e + 1.0f));
    return fmaf(-2.0f, r, 1.0f);
}

__device__ __constant__ float cA[5][5] = {
    {(float)(1.0 / 5.0), 0.f, 0.f, 0.f, 0.f},
    {(float)(3.0 / 40.0), (float)(9.0 / 40.0), 0.f, 0.f, 0.f},
    {(float)(44.0 / 45.0), (float)(-56.0 / 15.0), (float)(32.0 / 9.0), 0.f, 0.f},
    {(float)(19372.0 / 6561.0), (float)(-25360.0 / 2187.0),
     (float)(64448.0 / 6561.0), (float)(-212.0 / 729.0), 0.f},
    {(float)(9017.0 / 3168.0), (float)(-355.0 / 33.0),
     (float)(46732.0 / 5247.0), (float)(49.0 / 176.0),
     (float)(-5103.0 / 18656.0)},
};

__global__ void __launch_bounds__(TPB, 3)
ode_kernel(const float* __restrict__ y0, const float* __restrict__ ts,
           const float* __restrict__ W1, const float* __restrict__ b1,
           const float* __restrict__ W2, const float* __restrict__ b2,
           const float* __restrict__ W3, const float* __restrict__ b3,
           float* __restrict__ out) {
    __shared__ float dts[NT];
    __shared__ __align__(16) float hb[4][2][HH];   // [warp][m][k], warp-local

    const int tid = threadIdx.x;
    for (int i = tid; i < NT - 1; i += TPB) dts[i] = ts[i + 1] - ts[i];

    const int lane = tid & 31;
    const int wid = tid >> 5;
    const int jl = lane & 15;        // layer-1 unit quad selector
    const int mh = lane >> 4;        // this lane's element (0/1)
    const int j0 = 2 * lane;         // lane's 2 j's: j0, j0+1 (all 64 k)
    const int u0 = 4 * jl;           // layer-1 units u0..u0+3 for element mh

    // ---- W2 into registers: 2 j x 32 k-parity pairs (128 regs) ----
    u64 w2r[2][32];
#pragma unroll
    for (int jp = 0; jp < 2; jp++) {
        const float4* row = (const float4*)(W2 + (j0 + jp) * HH);
#pragma unroll
        for (int q = 0; q < 16; q++) {
            const float4 v = row[q];
            w2r[jp][2 * q]     = pk(v.x * L2E2, v.y * L2E2);
            w2r[jp][2 * q + 1] = pk(v.z * L2E2, v.w * L2E2);
        }
    }
    // ---- layer-1 weights for this lane's 4 units ----
    float w1x[4], w1y[4], b1r[4];
#pragma unroll
    for (int i = 0; i < 4; i++) {
        const int u = u0 + i;
        w1x[i] = W1[2 * u] * L2E2;
        w1y[i] = W1[2 * u + 1] * L2E2;
        b1r[i] = b1[u] * L2E2;
    }
    // ---- phase-D constants for this lane's 2 j's ----
    const float b2r0 = b2[j0] * L2E2;
    const float b2r1 = b2[j0 + 1] * L2E2;
    const u64 w3r0 = pk(W3[j0], W3[HH + j0]);
    const u64 w3r1 = pk(W3[j0 + 1], W3[HH + j0 + 1]);
    const u64 b3p = pk(b3[0], b3[1]);

    const int e0 = blockIdx.x * EPB + wid * 2;
    const int em = e0 + mh;          // lane's element
    u64 yv = ((const u64*)y0)[em];   // packed (yx, yy)
    u64* o8 = (u64*)out;
    if (jl == 0) o8[em] = yv;        // SaveAt includes the initial state
    __syncthreads();                 // dts ready (only block-wide sync)

    float* hw0 = &hb[wid][0][0];
    float* hw1 = &hb[wid][1][0];
    float* hme = mh ? hw1 : hw0;

    for (int t = 0; t < NT - 1; t++) {
        const float dtv = dts[t];
        const u64 dtp = dup2(dtv);
        u64 kreg[6];

#pragma unroll 1
        for (int st = 0; st < 6; st++) {
            // ---- stage input for this lane's element (packed) ----
            u64 sxy;
            if (st == 0) {
                sxy = yv;
            } else {
                u64 a = 0ull;
                for (int i = 0; i < st; i++)
                    a = fma2(dup2(cA[st - 1][i]), kreg[i], a);
                sxy = fma2(dtp, a, yv);
            }
            float sx, sy;
            upk(sxy, sx, sy);

            __syncwarp();   // prior stage's h readers done (WAR)

            // ---- layer 1: 4 units for element mh -> warp-local smem ----
            {
                float4 hv;
                hv.x = tanh_pre(fmaf(sx, w1x[0], fmaf(sy, w1y[0], b1r[0])));
                hv.y = tanh_pre(fmaf(sx, w1x[1], fmaf(sy, w1y[1], b1r[1])));
                hv.z = tanh_pre(fmaf(sx, w1x[2], fmaf(sy, w1y[2], b1r[2])));
                hv.w = tanh_pre(fmaf(sx, w1x[3], fmaf(sy, w1y[3], b1r[3])));
                *(float4*)&hme[u0] = hv;
            }
            __syncwarp();   // h complete (RAW)

            // ---- layer 2: reg weights x broadcast h, k-parity packed ----
            u64 a00 = 0ull, a01 = 0ull, a10 = 0ull, a11 = 0ull;
#pragma unroll
            for (int q = 0; q < 16; q++) {
                const float4 h0 = *(const float4*)&hw0[4 * q];
                const float4 h1 = *(const float4*)&hw1[4 * q];
                const u64 p0A = ((const u64*)&h0)[0], p0B = ((const u64*)&h0)[1];
                const u64 p1A = ((const u64*)&h1)[0], p1B = ((const u64*)&h1)[1];
                const u64 wA = w2r[0][2 * q], wB = w2r[0][2 * q + 1];
                const u64 vA = w2r[1][2 * q], vB = w2r[1][2 * q + 1];
                a00 = fma2(p0A, wA, a00);
                a01 = fma2(p0A, vA, a01);
                a10 = fma2(p1A, wA, a10);
                a11 = fma2(p1A, vA, a11);
                a00 = fma2(p0B, wB, a00);
                a01 = fma2(p0B, vB, a01);
                a10 = fma2(p1B, wB, a10);
                a11 = fma2(p1B, vB, a11);
            }

            // ---- phase D: merge parities, bias, tanh, layer 3 ----
            u64 accP[2];
            {
                float l, h;
                upk(a00, l, h);
                const float g0 = tanh_pre(l + h + b2r0);
                upk(a01, l, h);
                const float g1 = tanh_pre(l + h + b2r1);
                accP[0] = fma2(dup2(g0), w3r0, fma2(dup2(g1), w3r1, 0ull));
                upk(a10, l, h);
                const float g2 = tanh_pre(l + h + b2r0);
                upk(a11, l, h);
                const float g3 = tanh_pre(l + h + b2r1);
                accP[1] = fma2(dup2(g2), w3r0, fma2(dup2(g3), w3r1, 0ull));
            }

            // ---- split-butterfly: every lane ends with f(own element) ----
            const u64 give = mh ? accP[0] : accP[1];
            const u64 keep = mh ? accP[1] : accP[0];
            u64 s = add2(keep, shfl_xor64(give, 16));
            s = add2(s, shfl_xor64(s, 1));
            s = add2(s, shfl_xor64(s, 2));
            s = add2(s, shfl_xor64(s, 4));
            s = add2(s, shfl_xor64(s, 8));
            kreg[st] = add2(s, b3p);
        }

        // ---- combine and advance (packed) ----
        u64 comb = fma2(dup2((float)(35.0 / 384.0)), kreg[0], 0ull);
        comb = fma2(dup2((float)(500.0 / 1113.0)), kreg[2], comb);
        comb = fma2(dup2((float)(125.0 / 192.0)), kreg[3], comb);
        comb = fma2(dup2((float)(-2187.0 / 6784.0)), kreg[4], comb);
        comb = fma2(dup2((float)(11.0 / 84.0)), kreg[5], comb);
        yv = fma2(dtp, comb, yv);

        if (jl == 0)
            o8[(size_t)(t + 1) * NB + em] = yv;
    }
}

extern "C" void kernel_launch(void* const* d_in, const int* in_sizes, int n_in,
                              void* d_out, int out_size) {
    const float* y0 = (const float*)d_in[0];
    const float* ts = (const float*)d_in[1];
    const float* W1 = (const float*)d_in[2];
    const float* b1 = (const float*)d_in[3];
    const float* W2 = (const float*)d_in[4];
    const float* b2 = (const float*)d_in[5];
    const float* W3 = (const float*)d_in[6];
    const float* b3 = (const float*)d_in[7];
    ode_kernel<<<GRID, TPB>>>(y0, ts, W1, b1, W2, b2, W3, b3, (float*)d_out);
}